// round 17
// baseline (speedup 1.0000x reference)
#include <cuda_runtime.h>
#include <cuda_fp16.h>

#define Hh 96
#define Ww 96
#define TPB 384      // 12 warps: 3 M-strips (x32 rows) x 4 N-strips (x24 cols)
#define PAD 104      // halfs per smem row (208B stride: conflict-free ldmatrix)

typedef unsigned int u32;

static __device__ __forceinline__ u32 smem_u32(const void* p) {
    u32 a;
    asm("{ .reg .u64 t; cvta.to.shared.u64 t, %1; cvt.u32.u64 %0, t; }" : "=r"(a) : "l"(p));
    return a;
}

__global__ __launch_bounds__(TPB, 4) void conv_mma_kernel(
    const float* __restrict__ x, const float* __restrict__ pe,
    const float* __restrict__ wt, const float* __restrict__ bias,
    const float* __restrict__ rw, float* __restrict__ out, int C)
{
    __shared__ __align__(16) __half Bs[Hh * PAD];   // x + pe, K x N row-major (20KB)
    __shared__ __align__(16) u32 wpair[192];        // wpair[i] = (wcbig[i], wcbig[i+1]) fp16

    const int t  = threadIdx.x;
    const int bc = blockIdx.x;          // b*C + c
    const int c  = bc % C;

    const float* xp  = x + (size_t)bc * (Hh * Ww);
    const float* pep = pe + c * Hh;

    // wpair fill: wcbig[i] = wc[i mod 96], wc[k] = wt[c,k] + (k<3 ? rw[c,k] : 0).
    // A-frag register (h, j) == wpair[j - h + 96]; j-h+96 in [1, 191].
    if (t < 192) {
        int k1 = (t < 96) ? t : t - 96;
        int k2 = (t + 1 < 192) ? ((t + 1 < 96) ? t + 1 : t + 1 - 96) : 0;
        float w1 = wt[c * Hh + k1] + (k1 < 3 ? rw[c * 3 + k1] : 0.0f);
        float w2 = wt[c * Hh + k2] + (k2 < 3 ? rw[c * 3 + k2] : 0.0f);
        __half2 hp = __floats2half2_rn(w1, w2);
        wpair[t] = *(u32*)&hp;
    }

    // B fill: Bs[k][n] = fp16(x[k][n] + pe[k]),  K x N row-major, PAD stride
    #pragma unroll
    for (int i = t; i < (Hh * Ww) / 4; i += TPB) {
        float4 v = ((const float4*)xp)[i];
        int k = i / 24, n0 = (i % 24) * 4;
        float p = pep[k];
        __half2 h01 = __floats2half2_rn(v.x + p, v.y + p);
        __half2 h23 = __floats2half2_rn(v.z + p, v.w + p);
        *(uint2*)&Bs[k * PAD + n0] = make_uint2(*(u32*)&h01, *(u32*)&h23);
    }
    __syncthreads();            // single prep barrier

    // warp tiling: 32(M) x 24(N) per warp; B-frag shared by both m16-frags
    const int wid = t >> 5, lane = t & 31;
    const int mrow = (wid >> 2) * 32;       // 3 M-strips
    const int ncol = (wid & 3) * 24;        // 4 N-strips
    const int lr = lane & 15;

    const u32 sB = smem_u32(Bs);
    const float bv = bias[c];

    // A-frag base index: reg a0 of (mf=0, k6=0) reads wpair[cbase - hrow + 96]
    const int hrow  = mrow + (lane >> 2);   // fragment row (mf=0)
    const int cbase = (lane & 3) * 2;       // fragment k-col
    const int ib = cbase - hrow + 96;       // i0 = ib + k6*16 in [25,182]

    float acc[2][3][4];
    #pragma unroll
    for (int mf = 0; mf < 2; mf++)
        #pragma unroll
        for (int n = 0; n < 3; n++)
            #pragma unroll
            for (int q = 0; q < 4; q++) acc[mf][n][q] = bv;   // bias in acc init

    #pragma unroll
    for (int k6 = 0; k6 < 6; k6++) {
        // A fragments from the pair table; only 5 distinct entries per k6:
        // mf=0: {w0, wm8, wp8, w0}   mf=1 (i0-16): {wm16, wm24, wm8, wm16}
        const int i0 = ib + k6 * 16;
        u32 w0   = wpair[i0];
        u32 wm8  = wpair[i0 - 8];
        u32 wp8  = wpair[i0 + 8];
        u32 wm16 = wpair[i0 - 16];
        u32 wm24 = wpair[i0 - 24];
        #pragma unroll
        for (int n = 0; n < 3; n++) {
            u32 b0, b1;
            u32 baddr = sB + (u32)((k6 * 16 + lr) * PAD + ncol + n * 8) * 2;
            asm volatile("ldmatrix.sync.aligned.m8n8.x2.trans.shared.b16 {%0,%1}, [%2];"
                         : "=r"(b0), "=r"(b1) : "r"(baddr));
            asm volatile(
                "mma.sync.aligned.m16n8k16.row.col.f32.f16.f16.f32 "
                "{%0,%1,%2,%3}, {%4,%5,%6,%7}, {%8,%9}, {%0,%1,%2,%3};"
                : "+f"(acc[0][n][0]), "+f"(acc[0][n][1]),
                  "+f"(acc[0][n][2]), "+f"(acc[0][n][3])
                : "r"(w0), "r"(wm8), "r"(wp8), "r"(w0), "r"(b0), "r"(b1));
            asm volatile(
                "mma.sync.aligned.m16n8k16.row.col.f32.f16.f16.f32 "
                "{%0,%1,%2,%3}, {%4,%5,%6,%7}, {%8,%9}, {%0,%1,%2,%3};"
                : "+f"(acc[1][n][0]), "+f"(acc[1][n][1]),
                  "+f"(acc[1][n][2]), "+f"(acc[1][n][3])
                : "r"(wm16), "r"(wm24), "r"(wm8), "r"(wm16), "r"(b0), "r"(b1));
        }
    }

    // epilogue: per m-frag, rows lane/4 and lane/4+8, cols (lane%4)*2 (direct STG.64)
    float* op = out + (size_t)bc * (Hh * Ww);
    const int rbase = mrow + (lane >> 2);
    const int col0  = ncol + (lane & 3) * 2;
    #pragma unroll
    for (int mf = 0; mf < 2; mf++) {
        const int row = rbase + mf * 16;
        #pragma unroll
        for (int n = 0; n < 3; n++) {
            *(float2*)&op[row * Ww + col0 + n * 8]       = make_float2(acc[mf][n][0], acc[mf][n][1]);
            *(float2*)&op[(row + 8) * Ww + col0 + n * 8] = make_float2(acc[mf][n][2], acc[mf][n][3]);
        }
    }
}

extern "C" void kernel_launch(void* const* d_in, const int* in_sizes, int n_in,
                              void* d_out, int out_size) {
    const float* x    = (const float*)d_in[0];
    const float* pe   = (const float*)d_in[1];
    const float* wt   = (const float*)d_in[2];
    const float* bias = (const float*)d_in[3];
    const float* rw   = (const float*)d_in[4];
    float* out = (float*)d_out;

    const int nblocks = in_sizes[0] / (Hh * Ww);  // B*C = 4096
    const int C       = in_sizes[2] / Hh;         // 256

    conv_mma_kernel<<<nblocks, TPB>>>(x, pe, wt, bias, rw, out, C);
}